// round 1
// baseline (speedup 1.0000x reference)
#include <cuda_runtime.h>
#include <cstddef>

// ---------------- problem constants ----------------
#define DD   768          // model dim
#define MTOK 16           // memory tokens
#define SS   1024         // seq len
#define BB   16           // batch
#define TT   (SS + MTOK)  // kv len = 1040
#define NQ   (BB * SS)    // 16384 query rows
#define NKV  (BB * TT)    // 16640 kv rows
#define SCALE 0.036084391824351615f  // 1/sqrt(768)

// ---------------- scratch (device globals; no cudaMalloc allowed) ----------------
__device__ float g_kvin[(size_t)NKV * DD];   // [B*T, D]
__device__ float g_Q   [(size_t)NQ  * DD];   // [B*S, D]
__device__ float g_K   [(size_t)NKV * DD];   // [B*T, D]
__device__ float g_V   [(size_t)NKV * DD];   // [B*T, D]
__device__ float g_SC  [(size_t)BB * SS * TT]; // [B, S, T] scores / attn
__device__ float g_H   [(size_t)NQ  * DD];   // [B*S, D] head_out

// ---------------- kv concat: kvin[b,t] = t<S ? x[b,t] : memory[t-S] ----------------
__global__ void build_kvin(const float* __restrict__ x, const float* __restrict__ mem)
{
    const int VEC_TOTAL = NKV * (DD / 4);
    int idx = blockIdx.x * blockDim.x + threadIdx.x;
    if (idx >= VEC_TOTAL) return;
    int d4  = idx % (DD / 4);
    int row = idx / (DD / 4);
    int b = row / TT;
    int t = row % TT;
    const float4* src;
    if (t < SS)
        src = (const float4*)(x) + (size_t)(b * SS + t) * (DD / 4) + d4;
    else
        src = (const float4*)(mem) + (size_t)(t - SS) * (DD / 4) + d4;
    ((float4*)g_kvin)[idx] = *src;
}

// ---------------- GEMM NT: C[M,N] = A[M,K] * B[N,K]^T (+bias) ----------------
// 128x128 block tile, BK=8, 256 threads, 8x8 per-thread microkernel.
// M must be a multiple of 128, K a multiple of 8. N boundary handled (clamp loads, guard stores).
__global__ void __launch_bounds__(256, 2)
gemm_nt(const float* __restrict__ A, const float* __restrict__ B,
        const float* __restrict__ bias, float* __restrict__ C,
        int Mr, int Nc, int Kd,
        long long sA, long long sB, long long sC)
{
    A += (size_t)blockIdx.z * sA;
    B += (size_t)blockIdx.z * sB;
    C += (size_t)blockIdx.z * sC;

    __shared__ float As[8][128];
    __shared__ float Bs[8][128];

    const int tid = threadIdx.x;
    const int m0 = blockIdx.y * 128;
    const int n0 = blockIdx.x * 128;

    const int lr = tid >> 1;            // 0..127 tile row
    const int lc = (tid & 1) * 4;       // 0 or 4

    const float* Aptr = A + (size_t)(m0 + lr) * Kd + lc;
    int bn = n0 + lr; if (bn >= Nc) bn = Nc - 1;    // clamp OOB loads (N boundary)
    const float* Bptr = B + (size_t)bn * Kd + lc;

    const int tx = tid & 15;
    const int ty = tid >> 4;

    float acc[8][8];
    #pragma unroll
    for (int i = 0; i < 8; i++)
        #pragma unroll
        for (int j = 0; j < 8; j++) acc[i][j] = 0.0f;

    for (int k0 = 0; k0 < Kd; k0 += 8) {
        float4 av = *(const float4*)(Aptr + k0);
        float4 bv = *(const float4*)(Bptr + k0);
        As[lc + 0][lr] = av.x; As[lc + 1][lr] = av.y;
        As[lc + 2][lr] = av.z; As[lc + 3][lr] = av.w;
        Bs[lc + 0][lr] = bv.x; Bs[lc + 1][lr] = bv.y;
        Bs[lc + 2][lr] = bv.z; Bs[lc + 3][lr] = bv.w;
        __syncthreads();

        #pragma unroll
        for (int kk = 0; kk < 8; kk++) {
            float a[8], b[8];
            *(float4*)(a)     = *(const float4*)&As[kk][ty * 8];
            *(float4*)(a + 4) = *(const float4*)&As[kk][ty * 8 + 4];
            *(float4*)(b)     = *(const float4*)&Bs[kk][tx * 8];
            *(float4*)(b + 4) = *(const float4*)&Bs[kk][tx * 8 + 4];
            #pragma unroll
            for (int i = 0; i < 8; i++)
                #pragma unroll
                for (int j = 0; j < 8; j++)
                    acc[i][j] += a[i] * b[j];
        }
        __syncthreads();
    }

    #pragma unroll
    for (int i = 0; i < 8; i++) {
        const int m = m0 + ty * 8 + i;
        float* crow = C + (size_t)m * Nc;
        #pragma unroll
        for (int j = 0; j < 8; j++) {
            const int n = n0 + tx * 8 + j;
            if (n < Nc) {
                float v = acc[i][j];
                if (bias) v += bias[n];
                crow[n] = v;
            }
        }
    }
}

// ---------------- GEMM NN: C[M,N] = A[M,K] * B[K,N] ----------------
// Same tiling. All dims assumed aligned (M%128==0, N%128==0, K%8==0) for our uses.
__global__ void __launch_bounds__(256, 2)
gemm_nn(const float* __restrict__ A, const float* __restrict__ B,
        float* __restrict__ C,
        int Mr, int Nc, int Kd,
        long long sA, long long sB, long long sC)
{
    A += (size_t)blockIdx.z * sA;
    B += (size_t)blockIdx.z * sB;
    C += (size_t)blockIdx.z * sC;

    __shared__ float As[8][128];
    __shared__ float Bs[8][128];

    const int tid = threadIdx.x;
    const int m0 = blockIdx.y * 128;
    const int n0 = blockIdx.x * 128;

    // A load: same transposed pattern as NT
    const int lr = tid >> 1;
    const int lc = (tid & 1) * 4;
    const float* Aptr = A + (size_t)(m0 + lr) * Kd + lc;

    // B load: 8 k-rows x 128 n-cols, float4 along n
    const int kb  = tid >> 5;           // 0..7
    const int nb4 = (tid & 31) * 4;     // 0..124
    const float* Bptr = B + (size_t)kb * Nc + n0 + nb4;

    const int tx = tid & 15;
    const int ty = tid >> 4;

    float acc[8][8];
    #pragma unroll
    for (int i = 0; i < 8; i++)
        #pragma unroll
        for (int j = 0; j < 8; j++) acc[i][j] = 0.0f;

    for (int k0 = 0; k0 < Kd; k0 += 8) {
        float4 av = *(const float4*)(Aptr + k0);
        float4 bv = *(const float4*)(Bptr + (size_t)k0 * Nc);
        As[lc + 0][lr] = av.x; As[lc + 1][lr] = av.y;
        As[lc + 2][lr] = av.z; As[lc + 3][lr] = av.w;
        *(float4*)&Bs[kb][nb4] = bv;
        __syncthreads();

        #pragma unroll
        for (int kk = 0; kk < 8; kk++) {
            float a[8], b[8];
            *(float4*)(a)     = *(const float4*)&As[kk][ty * 8];
            *(float4*)(a + 4) = *(const float4*)&As[kk][ty * 8 + 4];
            *(float4*)(b)     = *(const float4*)&Bs[kk][tx * 8];
            *(float4*)(b + 4) = *(const float4*)&Bs[kk][tx * 8 + 4];
            #pragma unroll
            for (int i = 0; i < 8; i++)
                #pragma unroll
                for (int j = 0; j < 8; j++)
                    acc[i][j] += a[i] * b[j];
        }
        __syncthreads();
    }

    #pragma unroll
    for (int i = 0; i < 8; i++) {
        const int m = m0 + ty * 8 + i;
        float* crow = C + (size_t)m * Nc;
        #pragma unroll
        for (int j = 0; j < 8; j++)
            crow[n0 + tx * 8 + j] = acc[i][j];
    }
}

// ---------------- softmax over T=1040, fused scale + additive mask ----------------
__device__ __forceinline__ float warp_red_max(float v) {
    #pragma unroll
    for (int o = 16; o > 0; o >>= 1) v = fmaxf(v, __shfl_xor_sync(0xFFFFFFFFu, v, o));
    return v;
}
__device__ __forceinline__ float warp_red_sum(float v) {
    #pragma unroll
    for (int o = 16; o > 0; o >>= 1) v += __shfl_xor_sync(0xFFFFFFFFu, v, o);
    return v;
}

__global__ void __launch_bounds__(256)
softmax_rows(float* __restrict__ SC, const float* __restrict__ mask)
{
    const int row = blockIdx.x;          // 0..NQ-1
    const int s   = row % SS;
    float* r = SC + (size_t)row * TT;
    const float* mrow = mask + (size_t)s * TT;

    const int tid  = threadIdx.x;
    const int lane = tid & 31;
    const int warp = tid >> 5;
    __shared__ float red[8];

    float v[5];
    float mx = -1e30f;
    #pragma unroll
    for (int i = 0; i < 5; i++) {
        int t = tid + i * 256;
        if (t < TT) {
            float val = r[t] * SCALE + mrow[t];
            v[i] = val;
            mx = fmaxf(mx, val);
        } else v[i] = -1e30f;
    }
    // block max
    mx = warp_red_max(mx);
    if (lane == 0) red[warp] = mx;
    __syncthreads();
    if (warp == 0) {
        float x = (lane < 8) ? red[lane] : -1e30f;
        x = warp_red_max(x);
        if (lane == 0) red[0] = x;
    }
    __syncthreads();
    mx = red[0];
    __syncthreads();

    float sum = 0.0f;
    #pragma unroll
    for (int i = 0; i < 5; i++) {
        int t = tid + i * 256;
        if (t < TT) {
            float e = expf(v[i] - mx);
            v[i] = e;
            sum += e;
        }
    }
    // block sum
    sum = warp_red_sum(sum);
    if (lane == 0) red[warp] = sum;
    __syncthreads();
    if (warp == 0) {
        float x = (lane < 8) ? red[lane] : 0.0f;
        x = warp_red_sum(x);
        if (lane == 0) red[0] = x;
    }
    __syncthreads();
    const float inv = 1.0f / red[0];

    #pragma unroll
    for (int i = 0; i < 5; i++) {
        int t = tid + i * 256;
        if (t < TT) r[t] = v[i] * inv;
    }
}

// ---------------- launch ----------------
extern "C" void kernel_launch(void* const* d_in, const int* in_sizes, int n_in,
                              void* d_out, int out_size)
{
    const float* x    = (const float*)d_in[0];
    const float* mask = (const float*)d_in[1];
    const float* mem  = (const float*)d_in[2];
    const float* wq   = (const float*)d_in[3];
    const float* bq   = (const float*)d_in[4];
    const float* wk   = (const float*)d_in[5];
    const float* bk   = (const float*)d_in[6];
    const float* wv   = (const float*)d_in[7];
    const float* bv   = (const float*)d_in[8];
    const float* wo   = (const float*)d_in[9];
    const float* bo   = (const float*)d_in[10];
    float* out = (float*)d_out;

    float *kvin, *Q, *K, *V, *SC, *H;
    cudaGetSymbolAddress((void**)&kvin, g_kvin);
    cudaGetSymbolAddress((void**)&Q,    g_Q);
    cudaGetSymbolAddress((void**)&K,    g_K);
    cudaGetSymbolAddress((void**)&V,    g_V);
    cudaGetSymbolAddress((void**)&SC,   g_SC);
    cudaGetSymbolAddress((void**)&H,    g_H);

    // 1. kv concat
    {
        int total4 = NKV * (DD / 4);
        build_kvin<<<(total4 + 255) / 256, 256>>>(x, mem);
    }

    // 2. projections: rows x [768,768]^T
    gemm_nt<<<dim3(DD / 128, NQ  / 128, 1), 256>>>(x,    wq, bq, Q, NQ,  DD, DD, 0, 0, 0);
    gemm_nt<<<dim3(DD / 128, NKV / 128, 1), 256>>>(kvin, wk, bk, K, NKV, DD, DD, 0, 0, 0);
    gemm_nt<<<dim3(DD / 128, NKV / 128, 1), 256>>>(kvin, wv, bv, V, NKV, DD, DD, 0, 0, 0);

    // 3. scores[b] = Q[b] * K[b]^T    [1024 x 1040], batched over B
    gemm_nt<<<dim3((TT + 127) / 128, SS / 128, BB), 256>>>(
        Q, K, (const float*)nullptr, SC, SS, TT, DD,
        (long long)SS * DD, (long long)TT * DD, (long long)SS * TT);

    // 4. softmax with scale + mask
    softmax_rows<<<NQ, 256>>>(SC, mask);

    // 5. head_out[b] = attn[b] * V[b]   [1024 x 768]
    gemm_nn<<<dim3(DD / 128, SS / 128, BB), 256>>>(
        SC, V, H, SS, DD, TT,
        (long long)SS * TT, (long long)TT * DD, (long long)SS * DD);

    // 6. output projection -> d_out
    gemm_nt<<<dim3(DD / 128, NQ / 128, 1), 256>>>(H, wo, bo, out, NQ, DD, DD, 0, 0, 0);
}

// round 3
// speedup vs baseline: 3.4135x; 3.4135x over previous
#include <cuda_runtime.h>
#include <cuda_bf16.h>
#include <cstdint>
#include <cstddef>

// ---------------- problem constants ----------------
#define DD   768
#define MTOK 16
#define SS   1024
#define BB   16
#define TT   (SS + MTOK)   // 1040
#define TP   1152          // padded kv len (multiple of 128)
#define NQ   (BB * SS)     // 16384
#define NKV  (BB * TT)     // 16640
#define SCALE 0.036084391824351615f

// ---------------- scratch (device globals) ----------------
__device__ __align__(256) __nv_bfloat16 g_kvhi[(size_t)NKV * DD];
__device__ __align__(256) __nv_bfloat16 g_kvlo[(size_t)NKV * DD];
__device__ __align__(256) __nv_bfloat16 g_qhi [(size_t)NQ  * DD];
__device__ __align__(256) __nv_bfloat16 g_qlo [(size_t)NQ  * DD];
__device__ __align__(256) __nv_bfloat16 g_khi [(size_t)NKV * DD];
__device__ __align__(256) __nv_bfloat16 g_klo [(size_t)NKV * DD];
__device__ __align__(256) __nv_bfloat16 g_vthi[(size_t)BB * DD * TP];
__device__ __align__(256) __nv_bfloat16 g_vtlo[(size_t)BB * DD * TP];
__device__ __align__(256) float         g_sc  [(size_t)BB * SS * TP];
__device__ __align__(256) __nv_bfloat16 g_phi [(size_t)BB * SS * TP];
__device__ __align__(256) __nv_bfloat16 g_plo [(size_t)BB * SS * TP];
__device__ __align__(256) __nv_bfloat16 g_hhi [(size_t)NQ  * DD];
__device__ __align__(256) __nv_bfloat16 g_hlo [(size_t)NQ  * DD];
__device__ __align__(256) __nv_bfloat16 g_whi [4][(size_t)DD * DD];
__device__ __align__(256) __nv_bfloat16 g_wlo [4][(size_t)DD * DD];

// ---------------- helpers ----------------
__device__ __forceinline__ void bsplit(float f, __nv_bfloat16& h, __nv_bfloat16& l) {
    h = __float2bfloat16(f);
    l = __float2bfloat16(f - __bfloat162float(h));
}
__device__ __forceinline__ uint32_t smem_u32(const void* p) {
    uint32_t a;
    asm("{ .reg .u64 t; cvta.to.shared.u64 t, %1; cvt.u32.u64 %0, t; }" : "=r"(a) : "l"(p));
    return a;
}
__device__ __forceinline__ void cp16(uint32_t dst, const void* src) {
    asm volatile("cp.async.cg.shared.global [%0], [%1], 16;" :: "r"(dst), "l"(src));
}
__device__ __forceinline__ void cp_commit() {
    asm volatile("cp.async.commit_group;" ::: "memory");
}
template <int N>
__device__ __forceinline__ void cp_wait() {
    asm volatile("cp.async.wait_group %0;" :: "n"(N) : "memory");
}
__device__ __forceinline__ void ldm4(uint32_t* r, uint32_t addr) {
    asm volatile("ldmatrix.sync.aligned.m8n8.x4.shared.b16 {%0,%1,%2,%3},[%4];"
                 : "=r"(r[0]), "=r"(r[1]), "=r"(r[2]), "=r"(r[3]) : "r"(addr));
}
__device__ __forceinline__ void mma16816(float* c, const uint32_t* a, const uint32_t* b) {
    asm volatile("mma.sync.aligned.m16n8k16.row.col.f32.bf16.bf16.f32 "
                 "{%0,%1,%2,%3},{%4,%5,%6,%7},{%8,%9},{%0,%1,%2,%3};"
                 : "+f"(c[0]), "+f"(c[1]), "+f"(c[2]), "+f"(c[3])
                 : "r"(a[0]), "r"(a[1]), "r"(a[2]), "r"(a[3]), "r"(b[0]), "r"(b[1]));
}

// ---------------- elementwise prep ----------------
__global__ void build_kv(const float4* __restrict__ x, const float4* __restrict__ mem) {
    const int n4 = NKV * (DD / 4);
    int i = blockIdx.x * 256 + threadIdx.x;
    if (i >= n4) return;
    int d4  = i % (DD / 4);
    int row = i / (DD / 4);
    int b = row / TT, t = row % TT;
    float4 v = (t < SS) ? x[(size_t)(b * SS + t) * (DD / 4) + d4]
                        : mem[(size_t)(t - SS) * (DD / 4) + d4];
    union { __nv_bfloat16 bb[4]; uint2 u; } H, L;
    bsplit(v.x, H.bb[0], L.bb[0]);
    bsplit(v.y, H.bb[1], L.bb[1]);
    bsplit(v.z, H.bb[2], L.bb[2]);
    bsplit(v.w, H.bb[3], L.bb[3]);
    ((uint2*)g_kvhi)[i] = H.u;
    ((uint2*)g_kvlo)[i] = L.u;
}

__global__ void split4(const float4* __restrict__ s, uint2* __restrict__ hi,
                       uint2* __restrict__ lo, int n4) {
    int i = blockIdx.x * 256 + threadIdx.x;
    if (i >= n4) return;
    float4 v = s[i];
    union { __nv_bfloat16 bb[4]; uint2 u; } H, L;
    bsplit(v.x, H.bb[0], L.bb[0]);
    bsplit(v.y, H.bb[1], L.bb[1]);
    bsplit(v.z, H.bb[2], L.bb[2]);
    bsplit(v.w, H.bb[3], L.bb[3]);
    hi[i] = H.u;
    lo[i] = L.u;
}

// ---------------- HMMA split-bf16 GEMM ----------------
// C[M,N] = alpha*(A*B^T) (+bias) (+mask). A,B as hi/lo bf16 pairs, K-major.
// Block 128x128, BK=32, 256 threads (8 warps, 4x2), warp tile 32x64.
// SMEM row stride 40 elems (80B) -> conflict-free ldmatrix. 2-stage cp.async.

#define ROWB    80                  // bytes per smem row (40 bf16)
#define MATB    (128 * ROWB)        // 10240 bytes per matrix tile
#define STAGEB  (4 * MATB)          // Ahi,Alo,Bhi,Blo
#define GSMEM   (2 * STAGEB)        // 81920

__global__ void __launch_bounds__(256, 1)
gemm3(const __nv_bfloat16* __restrict__ Ahi, const __nv_bfloat16* __restrict__ Alo,
      long long sA, int ldA, int mrealA,
      const __nv_bfloat16* __restrict__ Bhi, const __nv_bfloat16* __restrict__ Blo,
      long long sB, int ldB, int nrealB,
      int K, float alpha,
      const float* __restrict__ bias, int bias_mode,   // 0 none, 1 over N, 2 over M
      const float* __restrict__ mask, int mask_ld, int mask_n,
      float* __restrict__ Cf, __nv_bfloat16* __restrict__ Chi, __nv_bfloat16* __restrict__ Clo,
      long long sC, int ldC)
{
    extern __shared__ char smem[];
    const uint32_t sb = smem_u32(smem);
    const int tid  = threadIdx.x;
    const int lane = tid & 31;
    const int warp = tid >> 5;
    const int wm = warp >> 1;          // 0..3
    const int wn = warp & 1;           // 0..1

    const int m0 = blockIdx.y * 128, n0 = blockIdx.x * 128;
    const __nv_bfloat16* pAh = Ahi + (size_t)blockIdx.z * sA;
    const __nv_bfloat16* pAl = Alo + (size_t)blockIdx.z * sA;
    const __nv_bfloat16* pBh = Bhi + (size_t)blockIdx.z * sB;
    const __nv_bfloat16* pBl = Blo + (size_t)blockIdx.z * sB;

    // ---- cp.async source/dest mapping: thread -> (row, half) ----
    const int r = tid >> 1;            // 0..127
    const int h = tid & 1;             // 16-elem half of 32-wide chunk
    int arow = m0 + r; if (arow >= mrealA) arow = mrealA - 1;
    int brow = n0 + r; if (brow >= nrealB) brow = nrealB - 1;
    const size_t aoff = (size_t)arow * ldA + h * 16;
    const size_t boff = (size_t)brow * ldB + h * 16;
    const uint32_t sdst = sb + (uint32_t)r * ROWB + (uint32_t)h * 32;

    float acc[2][8][4];
    #pragma unroll
    for (int i = 0; i < 2; i++)
        #pragma unroll
        for (int j = 0; j < 8; j++)
            #pragma unroll
            for (int q = 0; q < 4; q++) acc[i][j][q] = 0.0f;

    const int nchunk = K >> 5;

    // ---- prefetch chunk 0 ----
    {
        uint32_t d = sdst;
        cp16(d + 0 * MATB,      pAh + aoff); cp16(d + 0 * MATB + 16, pAh + aoff + 8);
        cp16(d + 1 * MATB,      pAl + aoff); cp16(d + 1 * MATB + 16, pAl + aoff + 8);
        cp16(d + 2 * MATB,      pBh + boff); cp16(d + 2 * MATB + 16, pBh + boff + 8);
        cp16(d + 3 * MATB,      pBl + boff); cp16(d + 3 * MATB + 16, pBl + boff + 8);
        cp_commit();
    }

    // ---- ldmatrix address bases (lane-dependent) ----
    const uint32_t a_r  = (uint32_t)(wm * 32 + (lane & 15));
    const uint32_t a_k  = (uint32_t)((lane >> 4) * 8);
    const uint32_t b_r  = (uint32_t)(wn * 64 + ((lane >> 4) & 1) * 8 + (lane & 7));
    const uint32_t b_k  = (uint32_t)(((lane >> 3) & 1) * 8);

    for (int c = 0; c < nchunk; c++) {
        if (c + 1 < nchunk) {
            const int k0 = (c + 1) << 5;
            uint32_t d = sdst + ((c + 1) & 1) * STAGEB;
            cp16(d + 0 * MATB,      pAh + aoff + k0); cp16(d + 0 * MATB + 16, pAh + aoff + k0 + 8);
            cp16(d + 1 * MATB,      pAl + aoff + k0); cp16(d + 1 * MATB + 16, pAl + aoff + k0 + 8);
            cp16(d + 2 * MATB,      pBh + boff + k0); cp16(d + 2 * MATB + 16, pBh + boff + k0 + 8);
            cp16(d + 3 * MATB,      pBl + boff + k0); cp16(d + 3 * MATB + 16, pBl + boff + k0 + 8);
            cp_commit();
            cp_wait<1>();
        } else {
            cp_wait<0>();
        }
        __syncthreads();

        const uint32_t base = sb + (c & 1) * STAGEB;
        #pragma unroll
        for (int ks = 0; ks < 2; ks++) {
            uint32_t ah[2][4], al[2][4];
            const uint32_t ka = (ks * 16 + a_k) * 2;
            ldm4(ah[0], base + 0 * MATB + (a_r     ) * ROWB + ka);
            ldm4(ah[1], base + 0 * MATB + (a_r + 16) * ROWB + ka);
            ldm4(al[0], base + 1 * MATB + (a_r     ) * ROWB + ka);
            ldm4(al[1], base + 1 * MATB + (a_r + 16) * ROWB + ka);

            const uint32_t kb = (ks * 16 + b_k) * 2;
            #pragma unroll
            for (int ntp = 0; ntp < 4; ntp++) {
                uint32_t bh[4], bl[4];
                ldm4(bh, base + 2 * MATB + (b_r + ntp * 16) * ROWB + kb);
                ldm4(bl, base + 3 * MATB + (b_r + ntp * 16) * ROWB + kb);
                #pragma unroll
                for (int mt = 0; mt < 2; mt++) {
                    mma16816(acc[mt][ntp * 2    ], ah[mt], bh);
                    mma16816(acc[mt][ntp * 2    ], ah[mt], bl);
                    mma16816(acc[mt][ntp * 2    ], al[mt], bh);
                    mma16816(acc[mt][ntp * 2 + 1], ah[mt], bh + 2);
                    mma16816(acc[mt][ntp * 2 + 1], ah[mt], bl + 2);
                    mma16816(acc[mt][ntp * 2 + 1], al[mt], bh + 2);
                }
            }
        }
        __syncthreads();
    }

    // ---- epilogue ----
    float* pC = Cf ? (Cf + (size_t)blockIdx.z * sC) : (float*)0;
    __nv_bfloat16* pCh = Chi ? (Chi + (size_t)blockIdx.z * sC) : (__nv_bfloat16*)0;
    __nv_bfloat16* pCl = Clo ? (Clo + (size_t)blockIdx.z * sC) : (__nv_bfloat16*)0;

    #pragma unroll
    for (int mt = 0; mt < 2; mt++) {
        #pragma unroll
        for (int nt = 0; nt < 8; nt++) {
            const int row0 = m0 + wm * 32 + mt * 16 + (lane >> 2);
            const int col  = n0 + wn * 64 + nt * 8 + (lane & 3) * 2;
            #pragma unroll
            for (int half = 0; half < 2; half++) {
                const int row = row0 + half * 8;
                float v0 = acc[mt][nt][half * 2    ] * alpha;
                float v1 = acc[mt][nt][half * 2 + 1] * alpha;
                if (bias_mode == 1) {
                    float2 bv = *(const float2*)(bias + col);
                    v0 += bv.x; v1 += bv.y;
                } else if (bias_mode == 2) {
                    float bm = bias[row];
                    v0 += bm; v1 += bm;
                }
                if (mask && col < mask_n) {
                    float2 mv = *(const float2*)(mask + (size_t)row * mask_ld + col);
                    v0 += mv.x; v1 += mv.y;
                }
                if (pC) {
                    float2 ov; ov.x = v0; ov.y = v1;
                    *(float2*)(pC + (size_t)row * ldC + col) = ov;
                } else {
                    __nv_bfloat16 h0, l0, h1, l1;
                    bsplit(v0, h0, l0);
                    bsplit(v1, h1, l1);
                    union { __nv_bfloat16 bb[2]; uint32_t u; } H, L;
                    H.bb[0] = h0; H.bb[1] = h1;
                    L.bb[0] = l0; L.bb[1] = l1;
                    *(uint32_t*)(pCh + (size_t)row * ldC + col) = H.u;
                    *(uint32_t*)(pCl + (size_t)row * ldC + col) = L.u;
                }
            }
        }
    }
}

// ---------------- softmax (scale+mask fused upstream) ----------------
__device__ __forceinline__ float wmax(float v) {
    #pragma unroll
    for (int o = 16; o > 0; o >>= 1) v = fmaxf(v, __shfl_xor_sync(0xFFFFFFFFu, v, o));
    return v;
}
__device__ __forceinline__ float wsum(float v) {
    #pragma unroll
    for (int o = 16; o > 0; o >>= 1) v += __shfl_xor_sync(0xFFFFFFFFu, v, o);
    return v;
}

__global__ void __launch_bounds__(256)
softmax_split(const float* __restrict__ SC, __nv_bfloat16* __restrict__ Phi,
              __nv_bfloat16* __restrict__ Plo)
{
    const size_t base = (size_t)blockIdx.x * TP;
    const float* rrow = SC + base;
    const int tid = threadIdx.x, lane = tid & 31, warp = tid >> 5;
    __shared__ float red[8];

    float v[5];
    float mx = -1e30f;
    #pragma unroll
    for (int i = 0; i < 5; i++) {
        int t = tid + i * 256;
        if (t < TT) { float x = rrow[t]; v[i] = x; mx = fmaxf(mx, x); }
        else v[i] = -1e30f;
    }
    mx = wmax(mx);
    if (lane == 0) red[warp] = mx;
    __syncthreads();
    if (warp == 0) {
        float x = (lane < 8) ? red[lane] : -1e30f;
        x = wmax(x);
        if (lane == 0) red[0] = x;
    }
    __syncthreads();
    mx = red[0];
    __syncthreads();

    float sum = 0.0f;
    #pragma unroll
    for (int i = 0; i < 5; i++) {
        int t = tid + i * 256;
        if (t < TT) { float e = expf(v[i] - mx); v[i] = e; sum += e; }
    }
    sum = wsum(sum);
    if (lane == 0) red[warp] = sum;
    __syncthreads();
    if (warp == 0) {
        float x = (lane < 8) ? red[lane] : 0.0f;
        x = wsum(x);
        if (lane == 0) red[0] = x;
    }
    __syncthreads();
    const float inv = 1.0f / red[0];

    #pragma unroll
    for (int i = 0; i < 5; i++) {
        int t = tid + i * 256;
        if (t < TT) {
            float p = v[i] * inv;
            __nv_bfloat16 hh, ll;
            bsplit(p, hh, ll);
            Phi[base + t] = hh;
            Plo[base + t] = ll;
        } else if (t < TP) {
            Phi[base + t] = __float2bfloat16(0.0f);
            Plo[base + t] = __float2bfloat16(0.0f);
        }
    }
}

// ---------------- launch ----------------
extern "C" void kernel_launch(void* const* d_in, const int* in_sizes, int n_in,
                              void* d_out, int out_size)
{
    const float* x    = (const float*)d_in[0];
    const float* mask = (const float*)d_in[1];
    const float* mem  = (const float*)d_in[2];
    const float* wq   = (const float*)d_in[3];
    const float* bq   = (const float*)d_in[4];
    const float* wk   = (const float*)d_in[5];
    const float* bk   = (const float*)d_in[6];
    const float* wv   = (const float*)d_in[7];
    const float* bv   = (const float*)d_in[8];
    const float* wo   = (const float*)d_in[9];
    const float* bo   = (const float*)d_in[10];
    float* out = (float*)d_out;

    __nv_bfloat16 *kvhi, *kvlo, *qhi, *qlo, *khi, *klo, *vthi, *vtlo, *phi, *plo, *hhi, *hlo;
    __nv_bfloat16 (*whi)[(size_t)DD * DD];
    __nv_bfloat16 (*wlo)[(size_t)DD * DD];
    float* sc;
    cudaGetSymbolAddress((void**)&kvhi, g_kvhi);
    cudaGetSymbolAddress((void**)&kvlo, g_kvlo);
    cudaGetSymbolAddress((void**)&qhi,  g_qhi);
    cudaGetSymbolAddress((void**)&qlo,  g_qlo);
    cudaGetSymbolAddress((void**)&khi,  g_khi);
    cudaGetSymbolAddress((void**)&klo,  g_klo);
    cudaGetSymbolAddress((void**)&vthi, g_vthi);
    cudaGetSymbolAddress((void**)&vtlo, g_vtlo);
    cudaGetSymbolAddress((void**)&sc,   g_sc);
    cudaGetSymbolAddress((void**)&phi,  g_phi);
    cudaGetSymbolAddress((void**)&plo,  g_plo);
    cudaGetSymbolAddress((void**)&hhi,  g_hhi);
    cudaGetSymbolAddress((void**)&hlo,  g_hlo);
    cudaGetSymbolAddress((void**)&whi,  g_whi);
    cudaGetSymbolAddress((void**)&wlo,  g_wlo);

    cudaFuncSetAttribute(gemm3, cudaFuncAttributeMaxDynamicSharedMemorySize, GSMEM);

    // 1. concat + split kv input
    {
        int n4 = NKV * (DD / 4);
        build_kv<<<(n4 + 255) / 256, 256>>>((const float4*)x, (const float4*)mem);
    }
    // 2. split weights
    {
        int w4 = DD * DD / 4;
        int gb = (w4 + 255) / 256;
        split4<<<gb, 256>>>((const float4*)wq, (uint2*)whi[0], (uint2*)wlo[0], w4);
        split4<<<gb, 256>>>((const float4*)wk, (uint2*)whi[1], (uint2*)wlo[1], w4);
        split4<<<gb, 256>>>((const float4*)wv, (uint2*)whi[2], (uint2*)wlo[2], w4);
        split4<<<gb, 256>>>((const float4*)wo, (uint2*)whi[3], (uint2*)wlo[3], w4);
    }

    // 3. Q = x * wq^T + bq (batched so A rows skip memory tokens)
    gemm3<<<dim3(DD / 128, SS / 128, BB), 256, GSMEM>>>(
        kvhi, kvlo, (long long)TT * DD, DD, SS,
        whi[0], wlo[0], 0, DD, DD,
        DD, 1.0f, bq, 1, nullptr, 0, 0,
        nullptr, qhi, qlo, (long long)SS * DD, DD);

    // 4. K = kv * wk^T + bk
    gemm3<<<dim3(DD / 128, NKV / 128, 1), 256, GSMEM>>>(
        kvhi, kvlo, 0, DD, NKV,
        whi[1], wlo[1], 0, DD, DD,
        DD, 1.0f, bk, 1, nullptr, 0, 0,
        nullptr, khi, klo, 0, DD);

    // 5. Vt[b] = wv * kv[b]^T + bv(rows)   [768 x TP]
    gemm3<<<dim3(TP / 128, DD / 128, BB), 256, GSMEM>>>(
        whi[2], wlo[2], 0, DD, DD,
        kvhi, kvlo, (long long)TT * DD, DD, TT,
        DD, 1.0f, bv, 2, nullptr, 0, 0,
        nullptr, vthi, vtlo, (long long)DD * TP, TP);

    // 6. scores[b] = SCALE * Q[b] K[b]^T + mask -> fp32
    gemm3<<<dim3(TP / 128, SS / 128, BB), 256, GSMEM>>>(
        qhi, qlo, (long long)SS * DD, DD, SS,
        khi, klo, (long long)TT * DD, DD, TT,
        DD, SCALE, nullptr, 0, mask, TT, TT,
        sc, nullptr, nullptr, (long long)SS * TP, TP);

    // 7. softmax -> split P (pad cols zeroed)
    softmax_split<<<NQ, 256>>>(sc, phi, plo);

    // 8. H[b] = P[b] * Vt[b]^T
    gemm3<<<dim3(DD / 128, SS / 128, BB), 256, GSMEM>>>(
        phi, plo, (long long)SS * TP, TP, SS,
        vthi, vtlo, (long long)DD * TP, TP, DD,
        TP, 1.0f, nullptr, 0, nullptr, 0, 0,
        nullptr, hhi, hlo, (long long)SS * DD, DD);

    // 9. out = H * wo^T + bo -> fp32 d_out
    gemm3<<<dim3(DD / 128, NQ / 128, 1), 256, GSMEM>>>(
        hhi, hlo, 0, DD, NQ,
        whi[3], wlo[3], 0, DD, DD,
        DD, 1.0f, bo, 1, nullptr, 0, 0,
        out, nullptr, nullptr, 0, DD);
}